// round 17
// baseline (speedup 1.0000x reference)
#include <cuda_runtime.h>
#include <math.h>

#define HH 2048
#define WW 2048
#define NF 64
#define MAXD 12
#define NSLOT 8191            // heap-ordered tree, depths 0..12
#define PXW 32                // patch width  (warp x-span)
#define PXH 4                 // patch height (rows per thread)
#define NPX (WW / PXW)        // 64
#define NPY (HH / PXH)        // 512
#define NPATCH (NPX * NPY)    // 32768

// Word encoding (per node):
//   bits [11:0]  split coordinate (interior) or 4095 sentinel (leaf)
//   bits [24:12] child base (interior: 2j+1) / self index (leaf: j -> self-loop)
//   bit  [25]    axis (1 = vertical/x split), 0 on leaves
//   bits [31:26] color index (leaf only)
// Fat node: g_tree4[j] = { word(j), word(left), word(right), 0 } -> 2 levels/LDG.128
__device__ int4   g_tree4[NSLOT];
__device__ float4 g_col[NF];        // leaf color table (read via __ldg, L1-hot)
// Per-patch record:
//   leaf patch   : { 0x80000000, bits(r), bits(g), bits(b) }   (color embedded)
//   crossed patch: { cur | pd<<16,  wj, wl, wr }               (first fat node embedded)
__device__ int4 g_pre[NPATCH];

__device__ __forceinline__ int make_word(int slot, int idx, int x0, int y0,
                                         int w, int h, int depth, const float* sr)
{
    if (depth == MAXD || w < 2 || h < 2)
        return 4095 | (slot << 12) | (idx << 26);            // leaf, self-loop
    int vert = idx & 1;
    int dim  = vert ? w : h;
    int cut  = max(1, (int)floorf((float)dim * sr[idx]));
    int s    = (vert ? x0 : y0) + cut;
    return s | ((2 * slot + 1) << 12) | (vert << 25);
}

// ---------------------------------------------------------------------------
// Kernel 1: fused tree build + color table + patch prefixes (independent
// roles by block, no synchronization). Blocks 0..31: fat tree (+ block 0
// fills g_col). Blocks 32..159: per-patch tree-free prefix walks.
// ---------------------------------------------------------------------------
__global__ __launch_bounds__(256) void k_build(
    const float* __restrict__ colors,
    const float* __restrict__ sel,
    const float* __restrict__ ratios)
{
    __shared__ float s_ratio[NF];
    __shared__ int   s_left[NF], s_right[NF];

    const int tid = threadIdx.x;
    const int b   = blockIdx.x;

    {   // argmax: row = tid>>1 (0..127), sub = tid&1 covers 32 elems.
        // First-max tie-break (strict >, lower index wins).
        const int row   = tid >> 1;
        const int sub   = tid & 1;
        const int frame = row >> 1;
        const int side  = row & 1;
        const float4* p = (const float4*)(sel + frame * 2 * NF + side * NF + sub * 32);

        float best = -3.4e38f; int bi = sub * 32;
        #pragma unroll
        for (int v4 = 0; v4 < 8; v4++) {
            float4 q = p[v4];
            float vv[4] = {q.x, q.y, q.z, q.w};
            #pragma unroll
            for (int e = 0; e < 4; e++) {
                int ii = sub * 32 + v4 * 4 + e;
                if (vv[e] > best) { best = vv[e]; bi = ii; }
            }
        }
        float ov = __shfl_xor_sync(0xffffffffu, best, 1);
        int   oi = __shfl_xor_sync(0xffffffffu, bi,   1);
        if (ov > best || (ov == best && oi < bi)) { best = ov; bi = oi; }
        if (sub == 0) { if (side == 0) s_left[frame] = bi; else s_right[frame] = bi; }
    }
    if (tid < NF) s_ratio[tid] = ratios[tid];
    if (b == 0 && tid < NF)
        g_col[tid] = make_float4(colors[3 * tid], colors[3 * tid + 1],
                                 colors[3 * tid + 2], 0.f);
    __syncthreads();

    if (b < 32) {
        // ---- fat tree build: thread j walks root -> slot j (branchless) ----
        const int j = b * 256 + tid;
        if (j >= NSLOT) return;

        const int depth = 31 - __clz(j + 1);    // 0..12
        int idx = 0, x0 = 0, y0 = 0, w = WW, h = HH;
        bool dead = false;

        for (int k = depth - 1; k >= 0; k--) {
            bool leaf = (w < 2) | (h < 2);
            dead = dead | leaf;
            int  bit  = ((j + 1) >> k) & 1;
            int  vert = idx & 1;
            float rt  = s_ratio[idx];
            int  dim  = vert ? w : h;
            int  cut  = max(1, (int)floorf((float)dim * rt));
            int  ndim = bit ? dim - cut : cut;
            int  oadd = bit ? cut : 0;
            int  nidx = bit ? s_right[idx] : s_left[idx];
            if (!dead) {
                if (vert) { x0 += oadd; w = ndim; }
                else      { y0 += oadd; h = ndim; }
                idx = nidx;
            }
        }
        if (dead) return;                       // unreachable slot, never read

        const bool jleaf = (depth == MAXD) || (w < 2) || (h < 2);
        int wj, wl, wr;
        if (jleaf) {
            wj = 4095 | (j << 12) | (idx << 26);
            wl = wj; wr = wj;                   // self-loop
        } else {
            int vert = idx & 1;
            int dim  = vert ? w : h;
            int cut  = max(1, (int)floorf((float)dim * s_ratio[idx]));
            int s    = (vert ? x0 : y0) + cut;
            wj = s | ((2 * j + 1) << 12) | (vert << 25);
            int li = s_left[idx], ri = s_right[idx];
            if (vert) {
                wl = make_word(2*j+1, li, x0,     y0, cut,   h, depth+1, s_ratio);
                wr = make_word(2*j+2, ri, x0+cut, y0, w-cut, h, depth+1, s_ratio);
            } else {
                wl = make_word(2*j+1, li, x0, y0,     w, cut,   depth+1, s_ratio);
                wr = make_word(2*j+2, ri, x0, y0+cut, w, h-cut, depth+1, s_ratio);
            }
        }
        g_tree4[j] = make_int4(wj, wl, wr, 0);
    } else {
        // ---- patch prefix (tree-free register walk) ----
        const int pid = (b - 32) * 256 + tid;   // 0..32767
        const int px0 = (pid & (NPX - 1)) * PXW;
        const int py0 = (pid >> 6) * PXH;

        int idx = 0, x0 = 0, y0 = 0, w = WW, h = HH, cur = 0, pd = 0;
        int4 rec;
        while (true) {
            if (pd == MAXD || w < 2 || h < 2) {  // patch inside a leaf -> embed RGB
                float r  = __ldg(&colors[3 * idx]);
                float g  = __ldg(&colors[3 * idx + 1]);
                float bl = __ldg(&colors[3 * idx + 2]);
                rec = make_int4((int)0x80000000, __float_as_int(r),
                                __float_as_int(g), __float_as_int(bl));
                break;
            }
            int vert = idx & 1;
            int dim  = vert ? w : h;
            int cut  = max(1, (int)floorf((float)dim * s_ratio[idx]));
            int s    = (vert ? x0 : y0) + cut;
            int lo   = vert ? px0 : py0;
            int hi   = lo + (vert ? PXW : PXH);
            if (hi <= s) {
                if (vert) w = cut; else h = cut;
                idx = s_left[idx];  cur = 2 * cur + 1; pd++;
            } else if (lo >= s) {
                if (vert) { x0 += cut; w -= cut; } else { y0 += cut; h -= cut; }
                idx = s_right[idx]; cur = 2 * cur + 2; pd++;
            } else {
                // split crosses patch -> embed this node's fat record
                int wj = s | ((2 * cur + 1) << 12) | (vert << 25);
                int li = s_left[idx], ri = s_right[idx];
                int wl, wr;
                if (vert) {
                    wl = make_word(2*cur+1, li, x0,     y0, cut,   h, pd+1, s_ratio);
                    wr = make_word(2*cur+2, ri, x0+cut, y0, w-cut, h, pd+1, s_ratio);
                } else {
                    wl = make_word(2*cur+1, li, x0, y0,     w, cut,   pd+1, s_ratio);
                    wr = make_word(2*cur+2, ri, x0, y0+cut, w, h-cut, pd+1, s_ratio);
                }
                rec = make_int4(cur | (pd << 16), wj, wl, wr);
                break;
            }
        }
        g_pre[pid] = rec;
    }
}

// ---------------------------------------------------------------------------
// Kernel 2: render. Warp = 32x4 patch, NO shared memory, NO block barrier —
// each warp's first instruction (after the PDL dependency sync) is its g_pre
// LDG.128. Leaf patch: pure stores from embedded RGB. Crossed patch: descent
// from the embedded fat node, (TRP-1) further fat-node loads, colors via
// __ldg(g_col). Launched with programmatic stream serialization so its
// launch/scheduling overlaps k_build.
// ---------------------------------------------------------------------------
__global__ __launch_bounds__(256) void k_render(float* __restrict__ out)
{
    const int px   = blockIdx.x;                        // 0..63
    const int py   = blockIdx.y * 8 + threadIdx.y;      // 0..511
    const int wy0  = py * PXH;
    const int x    = px * PXW + threadIdx.x;
    const int base = wy0 * WW + x;

#if __CUDA_ARCH__ >= 900
    cudaGridDependencySynchronize();                    // wait for k_build data
#endif

    const int4 pre = __ldg(&g_pre[py * NPX + px]);      // warp-uniform broadcast

    if (pre.x < 0) {                                    // leaf patch: RGB embedded
        const float r = __int_as_float(pre.y);
        const float g = __int_as_float(pre.z);
        const float b = __int_as_float(pre.w);
        #pragma unroll
        for (int q = 0; q < PXH; q++) {
            out[base + q * WW]               = r;
            out[HH * WW + base + q * WW]     = g;
            out[2 * HH * WW + base + q * WW] = b;
        }
        return;
    }

    const int pd  = pre.x >> 16;
    const int TRP = (MAXD - pd + 2) >> 1;               // pair iterations (>=1)
    const int4 nd0 = make_int4(pre.y, pre.z, pre.w, 0); // embedded first fat node

    float4 col = make_float4(0.f, 0.f, 0.f, 0.f);
    int reachy = -1;

    #pragma unroll
    for (int q = 0; q < PXH; q++) {
        const int y = wy0 + q;
        if (y >= reachy) {                              // warp-convergent trigger
            int4 nd = nd0;                              // level 1 from registers
            int ry = HH, vb = 0, c2 = 0;
            for (int i = 0; i < TRP; i++) {             // branchless, 2 levels/iter
                int  va = nd.x;
                int  sA = va & 0xFFF;
                bool vA = (va & (1 << 25)) != 0;
                bool gA = (vA ? x : y) >= sA;
                if (!gA && !vA) ry = min(ry, sA);
                vb = gA ? nd.z : nd.y;
                int  sB = vb & 0xFFF;
                bool vB = (vb & (1 << 25)) != 0;
                bool gB = (vB ? x : y) >= sB;
                if (!gB && !vB) ry = min(ry, sB);
                c2 = ((vb >> 12) & 0x1FFF) + (gB ? 1 : 0);
                if (i + 1 < TRP) nd = __ldg(&g_tree4[c2]);
            }
            col = __ldg(&g_col[(unsigned)vb >> 26]);
            reachy = ry;
        }
        out[base + q * WW]               = col.x;
        out[HH * WW + base + q * WW]     = col.y;
        out[2 * HH * WW + base + q * WW] = col.z;
    }
}

extern "C" void kernel_launch(void* const* d_in, const int* in_sizes, int n_in,
                              void* d_out, int out_size) {
    const float* colors = (const float*)d_in[0];   // frame_colors    [64, 3]
    const float* sel    = (const float*)d_in[1];   // frame_selection [64, 2, 64]
    const float* ratios = (const float*)d_in[2];   // split_ratios    [64]
    float* out = (float*)d_out;                    // [3, 2048, 2048] fp32

    k_build<<<160, 256>>>(colors, sel, ratios);    // blocks 0-31: tree; 32-159: prefixes

    // PDL: k_render launches while k_build drains; it syncs internally
    // before touching g_pre / g_tree4 / g_col.
    cudaLaunchConfig_t cfg = {};
    cfg.gridDim  = dim3(NPX, NPY / 8);             // 64 x 64 = 4096 blocks
    cfg.blockDim = dim3(32, 8);
    cudaLaunchAttribute attrs[1];
    attrs[0].id = cudaLaunchAttributeProgrammaticStreamSerialization;
    attrs[0].val.programmaticStreamSerializationAllowed = 1;
    cfg.attrs    = attrs;
    cfg.numAttrs = 1;
    cudaLaunchKernelEx(&cfg, k_render, out);
}